// round 13
// baseline (speedup 1.0000x reference)
#include <cuda_runtime.h>
#include <cuda_bf16.h>
#include <math.h>
#include <stdint.h>

#define Bb 2
#define LQ 1024
#define LKV 4096
#define Hh 1024
#define NHh 16
#define HD 64
#define MQ (Bb*LQ)        // 2048
#define MKV (Bb*LKV)      // 8192
#define NROWS (Bb*NHh*LQ) // 32768
#define NTILES 32         // LKV/128
#define LN_EPS 1e-12f
#define NEG_INF __int_as_float(0xff800000)

// ---------------- scratch (device globals; no allocation) ----------------
__device__ float g_Q[MQ*Hh];
__device__ float g_K[MKV*Hh];
__device__ float g_V[MKV*Hh];
__device__ float g_ctx[MQ*Hh];
__device__ float g_y[MQ*Hh];
__device__ float g_rmax[NROWS];
__device__ float g_rinv[NROWS];
__device__ float g_pmax[(size_t)NROWS*NTILES];
__device__ float g_psum[(size_t)NROWS*NTILES];
// V transposed + split: [bh][d(64)][chunk(64)][192 = hi64|hi64|lo64]
__device__ __nv_bfloat16 g_Vt[(size_t)Bb*NHh * 64 * 64 * 192];

// ================= HMMA helper =================
__device__ __forceinline__ void mma16816(float* d, const uint32_t* a,
                                         uint32_t b0, uint32_t b1) {
    asm volatile(
        "mma.sync.aligned.m16n8k16.row.col.f32.bf16.bf16.f32 "
        "{%0,%1,%2,%3}, {%4,%5,%6,%7}, {%8,%9}, {%0,%1,%2,%3};"
        : "+f"(d[0]), "+f"(d[1]), "+f"(d[2]), "+f"(d[3])
        : "r"(a[0]), "r"(a[1]), "r"(a[2]), "r"(a[3]), "r"(b0), "r"(b1));
}

#define AP 104

// prefetch 128x32 fp32 tile into 4 float4 regs per thread
__device__ __forceinline__ void pf_tile(const float* __restrict__ g, int ldg,
                                        float4* p, int tid)
{
#pragma unroll
    for (int i = 0; i < 4; i++) {
        int idx = tid + i * 256;
        int rr = idx >> 3, c4 = (idx & 7) * 4;
        p[i] = *(const float4*)&g[(size_t)rr * ldg + c4];
    }
}

// convert regs -> split bf16 smem tile (96 cols). modeB=0: [hi|lo|hi]; 1: [hi|hi|lo]
__device__ __forceinline__ void st_tile(const float4* p, __nv_bfloat16* __restrict__ s,
                                        int modeB, int tid)
{
#pragma unroll
    for (int i = 0; i < 4; i++) {
        int idx = tid + i * 256;
        int rr = idx >> 3, c4 = (idx & 7) * 4;
        float vv[4] = {p[i].x, p[i].y, p[i].z, p[i].w};
        __nv_bfloat16 hi[4], lo[4];
#pragma unroll
        for (int j = 0; j < 4; j++) {
            hi[j] = __float2bfloat16(vv[j]);
            lo[j] = __float2bfloat16(vv[j] - __bfloat162float(hi[j]));
        }
        __nv_bfloat162 h01, h23, l01, l23;
        h01.x = hi[0]; h01.y = hi[1]; h23.x = hi[2]; h23.y = hi[3];
        l01.x = lo[0]; l01.y = lo[1]; l23.x = lo[2]; l23.y = lo[3];
        __nv_bfloat16* o = s + rr * AP + c4;
        *(__nv_bfloat162*)(o)     = h01; *(__nv_bfloat162*)(o + 2)  = h23;
        if (modeB) {
            *(__nv_bfloat162*)(o + 32) = h01; *(__nv_bfloat162*)(o + 34) = h23;
            *(__nv_bfloat162*)(o + 64) = l01; *(__nv_bfloat162*)(o + 66) = l23;
        } else {
            *(__nv_bfloat162*)(o + 32) = l01; *(__nv_bfloat162*)(o + 34) = l23;
            *(__nv_bfloat162*)(o + 64) = h01; *(__nv_bfloat162*)(o + 66) = h23;
        }
    }
}

// 96-col k-loop, warp tile 64x32
__device__ __forceinline__ void mma_chunk96(const __nv_bfloat16* As, const __nv_bfloat16* Bs,
                                            int wm, int wn, int r, int cq, float acc[4][4][4])
{
#pragma unroll
    for (int kk = 0; kk < 96; kk += 16) {
        uint32_t af[4][4];
#pragma unroll
        for (int mt = 0; mt < 4; mt++) {
            const __nv_bfloat16* ab = &As[(wm + mt*16 + r)*AP + kk + cq*2];
            af[mt][0] = *(const uint32_t*)(ab);
            af[mt][1] = *(const uint32_t*)(ab + 8*AP);
            af[mt][2] = *(const uint32_t*)(ab + 8);
            af[mt][3] = *(const uint32_t*)(ab + 8*AP + 8);
        }
#pragma unroll
        for (int nt = 0; nt < 4; nt++) {
            const __nv_bfloat16* bb = &Bs[(wn + nt*8 + r)*AP + kk + cq*2];
            uint32_t b0 = *(const uint32_t*)(bb);
            uint32_t b1 = *(const uint32_t*)(bb + 8);
#pragma unroll
            for (int mt = 0; mt < 4; mt++)
                mma16816(acc[mt][nt], af[mt], b0, b1);
        }
    }
}

// ================= projection GEMM (pipelined, double-buffered) =================
#define PROJ_SMEM (4*128*AP*2)
__global__ __launch_bounds__(256, 1) void proj_gemm(
    const float* __restrict__ X, const float* __restrict__ W,
    const float* __restrict__ bias, const float* __restrict__ res,
    float* __restrict__ out)
{
    extern __shared__ __nv_bfloat16 sm[];
    __nv_bfloat16* Asb[2] = { sm,            sm + 2*128*AP };
    __nv_bfloat16* Bsb[2] = { sm + 128*AP,   sm + 3*128*AP };
    __shared__ float stage[128];
    const int tid = threadIdx.x, warp = tid >> 5, lane = tid & 31;
    const int m0 = blockIdx.y * 128, n0 = blockIdx.x * 128;
    const float* Ap = X + (size_t)m0 * Hh;
    const float* Bp = W + (size_t)n0 * Hh;

    if (tid < 128) stage[tid] = bias[n0 + tid];

    const int wm = (warp >> 2) * 64, wn = (warp & 3) * 32;
    const int r = lane >> 2, cq = lane & 3;

    float acc[4][4][4];
#pragma unroll
    for (int mt = 0; mt < 4; mt++)
#pragma unroll
        for (int nt = 0; nt < 4; nt++)
#pragma unroll
            for (int j = 0; j < 4; j++) acc[mt][nt][j] = 0.f;

    float4 pa[4], pb[4];
    pf_tile(Ap, Hh, pa, tid);
    pf_tile(Bp, Hh, pb, tid);
    st_tile(pa, Asb[0], 0, tid);
    st_tile(pb, Bsb[0], 1, tid);
    pf_tile(Ap + 32, Hh, pa, tid);
    pf_tile(Bp + 32, Hh, pb, tid);
    __syncthreads();

    for (int c = 0; c < 32; c++) {
        if (c + 1 < 32) {
            st_tile(pa, Asb[(c+1)&1], 0, tid);
            st_tile(pb, Bsb[(c+1)&1], 1, tid);
        }
        if (c + 2 < 32) {
            pf_tile(Ap + (c+2)*32, Hh, pa, tid);
            pf_tile(Bp + (c+2)*32, Hh, pb, tid);
        }
        mma_chunk96(Asb[c&1], Bsb[c&1], wm, wn, r, cq, acc);
        __syncthreads();
    }

#pragma unroll
    for (int mt = 0; mt < 4; mt++) {
        const int mA = m0 + wm + mt*16 + r;
#pragma unroll
        for (int nt = 0; nt < 4; nt++) {
            const int nl = wn + nt*8 + cq*2;
            const int nA = n0 + nl;
            float bx = stage[nl], by = stage[nl + 1];
            float2 v0, v1;
            v0.x = acc[mt][nt][0] + bx; v0.y = acc[mt][nt][1] + by;
            v1.x = acc[mt][nt][2] + bx; v1.y = acc[mt][nt][3] + by;
            if (res) {
                float2 r0 = *(const float2*)&res[(size_t)mA * Hh + nA];
                float2 r1 = *(const float2*)&res[(size_t)(mA+8) * Hh + nA];
                v0.x += r0.x; v0.y += r0.y; v1.x += r1.x; v1.y += r1.y;
            }
            *(float2*)&out[(size_t)mA * Hh + nA]     = v0;
            *(float2*)&out[(size_t)(mA+8) * Hh + nA] = v1;
        }
    }
}

// ================= scores + per-block softmax partials (both chunks staged) =================
#define SC_SMEM (4*128*AP*2)
__global__ __launch_bounds__(256, 1) void scores_stats(
    const float* __restrict__ Qf, const float* __restrict__ Kf,
    const int* __restrict__ mask, float* __restrict__ S,
    float* __restrict__ pmax, float* __restrict__ psum)
{
    extern __shared__ __nv_bfloat16 sm[];
    __nv_bfloat16* Asb[2] = { sm,            sm + 2*128*AP };
    __nv_bfloat16* Bsb[2] = { sm + 128*AP,   sm + 3*128*AP };
    __shared__ int maskS[128];
    __shared__ float rpart[4][128];
    __shared__ float bmax[128];
    const int tid = threadIdx.x, warp = tid >> 5, lane = tid & 31;
    const int kv0 = blockIdx.x * 128, q0 = blockIdx.y * 128, bh = blockIdx.z;
    const int b = bh >> 4, h = bh & 15;

    const float* Ap = Qf + ((size_t)(b*LQ  + q0 )) * Hh + h*64;
    const float* Bp = Kf + ((size_t)(b*LKV + kv0)) * Hh + h*64;
    float* Sb = S + (size_t)bh * LQ * LKV;

    if (tid < 128) maskS[tid] = mask[b*LKV + kv0 + tid];

    const int wm = (warp >> 2) * 64, wn = (warp & 3) * 32;
    const int r = lane >> 2, cq = lane & 3;

    float acc[4][4][4];
#pragma unroll
    for (int mt = 0; mt < 4; mt++)
#pragma unroll
        for (int nt = 0; nt < 4; nt++)
#pragma unroll
            for (int j = 0; j < 4; j++) acc[mt][nt][j] = 0.f;

    {
        float4 pa[4], pb[4];
        pf_tile(Ap, Hh, pa, tid);
        pf_tile(Bp, Hh, pb, tid);
        st_tile(pa, Asb[0], 0, tid);
        st_tile(pb, Bsb[0], 1, tid);
        pf_tile(Ap + 32, Hh, pa, tid);
        pf_tile(Bp + 32, Hh, pb, tid);
        st_tile(pa, Asb[1], 0, tid);
        st_tile(pb, Bsb[1], 1, tid);
    }
    __syncthreads();
    mma_chunk96(Asb[0], Bsb[0], wm, wn, r, cq, acc);
    mma_chunk96(Asb[1], Bsb[1], wm, wn, r, cq, acc);

#pragma unroll
    for (int mt = 0; mt < 4; mt++) {
        const int lm = wm + mt*16 + r;
#pragma unroll
        for (int nt = 0; nt < 4; nt++) {
            const int nl = wn + nt*8 + cq*2;
            int mx = maskS[nl], my = maskS[nl + 1];
            acc[mt][nt][0] = mx ? acc[mt][nt][0] * 0.125f : NEG_INF;
            acc[mt][nt][1] = my ? acc[mt][nt][1] * 0.125f : NEG_INF;
            acc[mt][nt][2] = mx ? acc[mt][nt][2] * 0.125f : NEG_INF;
            acc[mt][nt][3] = my ? acc[mt][nt][3] * 0.125f : NEG_INF;
            float2 v0, v1;
            v0.x = acc[mt][nt][0]; v0.y = acc[mt][nt][1];
            v1.x = acc[mt][nt][2]; v1.y = acc[mt][nt][3];
            *(float2*)&Sb[(size_t)(q0 + lm)     * LKV + kv0 + nl] = v0;
            *(float2*)&Sb[(size_t)(q0 + lm + 8) * LKV + kv0 + nl] = v1;
        }
    }

#pragma unroll
    for (int mt = 0; mt < 4; mt++) {
#pragma unroll
        for (int half = 0; half < 2; half++) {
            float mrow = NEG_INF;
#pragma unroll
            for (int nt = 0; nt < 4; nt++) {
                mrow = fmaxf(mrow, acc[mt][nt][2*half + 0]);
                mrow = fmaxf(mrow, acc[mt][nt][2*half + 1]);
            }
            mrow = fmaxf(mrow, __shfl_xor_sync(0xFFFFFFFF, mrow, 1));
            mrow = fmaxf(mrow, __shfl_xor_sync(0xFFFFFFFF, mrow, 2));
            if (cq == 0) rpart[warp & 3][wm + mt*16 + r + half*8] = mrow;
        }
    }
    __syncthreads();
    if (tid < 128)
        bmax[tid] = fmaxf(fmaxf(rpart[0][tid], rpart[1][tid]),
                          fmaxf(rpart[2][tid], rpart[3][tid]));
    __syncthreads();

#pragma unroll
    for (int mt = 0; mt < 4; mt++) {
#pragma unroll
        for (int half = 0; half < 2; half++) {
            const int row = wm + mt*16 + r + half*8;
            const float bm = bmax[row];
            float srow = 0.f;
#pragma unroll
            for (int nt = 0; nt < 4; nt++) {
#pragma unroll
                for (int j = 0; j < 2; j++) {
                    float v = acc[mt][nt][2*half + j];
                    srow += (v == NEG_INF) ? 0.f : __expf(v - bm);
                }
            }
            srow += __shfl_xor_sync(0xFFFFFFFF, srow, 1);
            srow += __shfl_xor_sync(0xFFFFFFFF, srow, 2);
            if (cq == 0) rpart[warp & 3][row] = srow;
        }
    }
    __syncthreads();
    if (tid < 128) {
        float ssum = rpart[0][tid] + rpart[1][tid] + rpart[2][tid] + rpart[3][tid];
        size_t grow = (size_t)bh * LQ + q0 + tid;
        pmax[grow * NTILES + blockIdx.x] = bmax[tid];
        psum[grow * NTILES + blockIdx.x] = ssum;
    }
}

// ================= combine partial stats =================
__global__ __launch_bounds__(256) void stats_reduce(
    const float* __restrict__ pmax, const float* __restrict__ psum)
{
    const int row = blockIdx.x * 8 + (threadIdx.x >> 5);
    const int lane = threadIdx.x & 31;
    float pm = pmax[(size_t)row * NTILES + lane];
    float ps = psum[(size_t)row * NTILES + lane];
    float m = pm;
#pragma unroll
    for (int off = 16; off > 0; off >>= 1)
        m = fmaxf(m, __shfl_xor_sync(0xFFFFFFFF, m, off));
    float term = (ps > 0.f) ? ps * __expf(pm - m) : 0.f;
#pragma unroll
    for (int off = 16; off > 0; off >>= 1)
        term += __shfl_xor_sync(0xFFFFFFFF, term, off);
    if (lane == 0) { g_rmax[row] = m; g_rinv[row] = 1.0f / term; }
}

// ================= V transpose + split =================
__global__ __launch_bounds__(256) void splitT_v(const float* __restrict__ V,
                                                __nv_bfloat16* __restrict__ vt)
{
    __shared__ float t[64 * 65];
    const int bh = blockIdx.y, c = blockIdx.x;
    const int b = bh >> 4, h = bh & 15;
    const int tid = threadIdx.x;
    const float* src = V + ((size_t)b * LKV + c * 64) * Hh + h * 64;
#pragma unroll
    for (int i = 0; i < 16; i++) {
        int idx = tid + i * 256;
        int kv = idx >> 6, d = idx & 63;
        t[kv * 65 + d] = src[(size_t)kv * Hh + d];
    }
    __syncthreads();
#pragma unroll
    for (int i = 0; i < 16; i++) {
        int idx = tid + i * 256;
        int d = idx >> 6, kv = idx & 63;
        float x = t[kv * 65 + d];
        __nv_bfloat16 hi = __float2bfloat16(x);
        __nv_bfloat16 lo = __float2bfloat16(x - __bfloat162float(hi));
        __nv_bfloat16* base = vt + (((size_t)bh * 64 + d) * 64 + c) * 192;
        base[kv]       = hi;
        base[64 + kv]  = hi;
        base[128 + kv] = lo;
    }
}

// ---------------- ctx = softmax(S) @ V  (HMMA, fused exp, reg-prefetched) ----------------
#define CP 200
#define CTX_SMEM (128*CP*2 + 64*CP*2 + 2*128*4)
__global__ __launch_bounds__(256, 1) void ctx_hmma(const float* __restrict__ S,
                                                   const __nv_bfloat16* __restrict__ vt)
{
    extern __shared__ char csm[];
    __nv_bfloat16* As = (__nv_bfloat16*)csm;
    __nv_bfloat16* Bs = As + 128 * CP;
    float* rm = (float*)(Bs + 64 * CP);
    float* ri = rm + 128;

    const int tid = threadIdx.x, warp = tid >> 5, lane = tid & 31;
    const int bh = blockIdx.y, q0 = blockIdx.x * 128;
    const int b = bh >> 4, h = bh & 15;
    const int rowbase = bh * LQ + q0;

    if (tid < 128) { rm[tid] = g_rmax[rowbase + tid]; ri[tid] = g_rinv[rowbase + tid]; }
    __syncthreads();

    const float* Srow = S + (size_t)rowbase * LKV;
    const __nv_bfloat16* vtb = vt + (size_t)bh * 64 * 64 * 192;
    const int wm = (warp >> 1) * 32, wn = (warp & 1) * 32;
    const int r = lane >> 2, cq = lane & 3;

    float acc[2][4][4];
#pragma unroll
    for (int mt = 0; mt < 2; mt++)
#pragma unroll
        for (int nt = 0; nt < 4; nt++)
#pragma unroll
            for (int j = 0; j < 4; j++) acc[mt][nt][j] = 0.f;

    float4 ps[8];
    uint4  pv[6];
    // prefetch chunk 0
#pragma unroll
    for (int i = 0; i < 8; i++) {
        int idx = tid + i * 256;
        int q = idx >> 4, j = (idx & 15) * 4;
        ps[i] = *(const float4*)&Srow[(size_t)q * LKV + j];
    }
#pragma unroll
    for (int i = 0; i < 6; i++) {
        int idx = tid + i * 256;
        int d = idx / 24, v = (idx % 24) * 8;
        pv[i] = *(const uint4*)&vtb[((size_t)d * 64) * 192 + v];
    }

    for (int c = 0; c < 64; c++) {
        // convert + store current chunk from regs
#pragma unroll
        for (int i = 0; i < 8; i++) {
            int idx = tid + i * 256;
            int q = idx >> 4, j = (idx & 15) * 4;
            float mq = rm[q], iq = ri[q];
            float p0 = __expf(ps[i].x - mq) * iq;
            float p1 = __expf(ps[i].y - mq) * iq;
            float p2 = __expf(ps[i].z - mq) * iq;
            float p3 = __expf(ps[i].w - mq) * iq;
            __nv_bfloat16 h0 = __float2bfloat16(p0), h1 = __float2bfloat16(p1);
            __nv_bfloat16 h2 = __float2bfloat16(p2), h3 = __float2bfloat16(p3);
            __nv_bfloat162 h01; h01.x = h0; h01.y = h1;
            __nv_bfloat162 h23; h23.x = h2; h23.y = h3;
            __nv_bfloat162 l01, l23;
            l01.x = __float2bfloat16(p0 - __bfloat162float(h0));
            l01.y = __float2bfloat16(p1 - __bfloat162float(h1));
            l23.x = __float2bfloat16(p2 - __bfloat162float(h2));
            l23.y = __float2bfloat16(p3 - __bfloat162float(h3));
            __nv_bfloat16* base = &As[q * CP];
            *(__nv_bfloat162*)(base + j)       = h01; *(__nv_bfloat162*)(base + j + 2)       = h23;
            *(__nv_bfloat162*)(base + 64 + j)  = l01; *(__nv_bfloat162*)(base + 64 + j + 2)  = l23;
            *(__nv_bfloat162*)(base + 128 + j) = h01; *(__nv_bfloat162*)(base + 128 + j + 2) = h23;
        }
#pragma unroll
        for (int i = 0; i < 6; i++) {
            int idx = tid + i * 256;
            int d = idx / 24, v = (idx % 24) * 8;
            *(uint4*)&Bs[d * CP + v] = pv[i];
        }
        __syncthreads();
        // prefetch next chunk (LDG latency hides under MMA below)
        if (c + 1 < 64) {
#pragma unroll
            for (int i = 0; i < 8; i++) {
                int idx = tid + i * 256;
                int q = idx >> 4, j = (idx & 15) * 4;
                ps[i] = *(const float4*)&Srow[(size_t)q * LKV + (c+1) * 64 + j];
            }
#pragma unroll
            for (int i = 0; i < 6; i++) {
                int idx = tid + i * 256;
                int d = idx / 24, v = (idx % 24) * 8;
                pv[i] = *(const uint4*)&vtb[((size_t)d * 64 + (c+1)) * 192 + v];
            }
        }
#pragma unroll
        for (int kk = 0; kk < 192; kk += 16) {
            uint32_t af[2][4];
#pragma unroll
            for (int mt = 0; mt < 2; mt++) {
                const __nv_bfloat16* ab = &As[(wm + mt*16 + r) * CP + kk + cq*2];
                af[mt][0] = *(const uint32_t*)(ab);
                af[mt][1] = *(const uint32_t*)(ab + 8*CP);
                af[mt][2] = *(const uint32_t*)(ab + 8);
                af[mt][3] = *(const uint32_t*)(ab + 8*CP + 8);
            }
#pragma unroll
            for (int nt = 0; nt < 4; nt++) {
                const __nv_bfloat16* bb = &Bs[(wn + nt*8 + r) * CP + kk + cq*2];
                uint32_t b0 = *(const uint32_t*)(bb);
                uint32_t b1 = *(const uint32_t*)(bb + 8);
#pragma unroll
                for (int mt = 0; mt < 2; mt++)
                    mma16816(acc[mt][nt], af[mt], b0, b1);
            }
        }
        __syncthreads();
    }

#pragma unroll
    for (int mt = 0; mt < 2; mt++) {
        const int q = q0 + wm + mt*16 + r;
#pragma unroll
        for (int nt = 0; nt < 4; nt++) {
            const int d = wn + nt*8 + cq*2;
            float2 v0, v1;
            v0.x = acc[mt][nt][0]; v0.y = acc[mt][nt][1];
            v1.x = acc[mt][nt][2]; v1.y = acc[mt][nt][3];
            *(float2*)&g_ctx[((size_t)(b*LQ + q))     * Hh + h*64 + d] = v0;
            *(float2*)&g_ctx[((size_t)(b*LQ + q + 8)) * Hh + h*64 + d] = v1;
        }
    }
}

// ---------------- layernorm over last dim ----------------
__global__ __launch_bounds__(256) void ln_kernel(
    const float* __restrict__ Y, const float* __restrict__ w,
    const float* __restrict__ bta, float* __restrict__ out)
{
    const int row = blockIdx.x;
    __shared__ float buf[Hh];
    __shared__ float red[256];
    const int tid = threadIdx.x;
    const float* y = Y + (size_t)row * Hh;

    float s = 0.f;
    for (int i = tid; i < Hh; i += 256) { float v = y[i]; buf[i] = v; s += v; }
    red[tid] = s; __syncthreads();
    for (int st = 128; st > 0; st >>= 1) {
        if (tid < st) red[tid] += red[tid + st];
        __syncthreads();
    }
    const float mu = red[0] * (1.0f / Hh); __syncthreads();

    float vs = 0.f;
    for (int i = tid; i < Hh; i += 256) { float dd = buf[i] - mu; vs += dd * dd; }
    red[tid] = vs; __syncthreads();
    for (int st = 128; st > 0; st >>= 1) {
        if (tid < st) red[tid] += red[tid + st];
        __syncthreads();
    }
    const float inv = rsqrtf(red[0] * (1.0f / Hh) + LN_EPS);

    for (int i = tid; i < Hh; i += 256)
        out[(size_t)row * Hh + i] = (buf[i] - mu) * inv * w[i] + bta[i];
}

// ---------------- launch ----------------
extern "C" void kernel_launch(void* const* d_in, const int* in_sizes, int n_in,
                              void* d_out, int out_size)
{
    (void)in_sizes; (void)n_in; (void)out_size;
    const float* hs   = (const float*)d_in[0];
    const float* ehs  = (const float*)d_in[1];
    const int*   mask = (const int*)  d_in[2];
    const float* q_w  = (const float*)d_in[3];
    const float* q_b  = (const float*)d_in[4];
    const float* k_w  = (const float*)d_in[5];
    const float* k_b  = (const float*)d_in[6];
    const float* v_w  = (const float*)d_in[7];
    const float* v_b  = (const float*)d_in[8];
    const float* o_w  = (const float*)d_in[9];
    const float* o_b  = (const float*)d_in[10];
    const float* ln_w = (const float*)d_in[11];
    const float* ln_b = (const float*)d_in[12];

    float* out  = (float*)d_out;
    float* Sout = out + (size_t)MQ * Hh;

    float *pQ, *pK, *pV, *pCtx, *pY, *pPmax, *pPsum;
    cudaGetSymbolAddress((void**)&pQ,    g_Q);
    cudaGetSymbolAddress((void**)&pK,    g_K);
    cudaGetSymbolAddress((void**)&pV,    g_V);
    cudaGetSymbolAddress((void**)&pCtx,  g_ctx);
    cudaGetSymbolAddress((void**)&pY,    g_y);
    cudaGetSymbolAddress((void**)&pPmax, g_pmax);
    cudaGetSymbolAddress((void**)&pPsum, g_psum);
    __nv_bfloat16* pVt;
    cudaGetSymbolAddress((void**)&pVt, g_Vt);

    cudaFuncSetAttribute(proj_gemm,    cudaFuncAttributeMaxDynamicSharedMemorySize, PROJ_SMEM);
    cudaFuncSetAttribute(scores_stats, cudaFuncAttributeMaxDynamicSharedMemorySize, SC_SMEM);
    cudaFuncSetAttribute(ctx_hmma,     cudaFuncAttributeMaxDynamicSharedMemorySize, CTX_SMEM);

    // 1) projections (HMMA, pipelined)
    proj_gemm<<<dim3(8, MQ/128),  256, PROJ_SMEM>>>(hs,  q_w, q_b, nullptr, pQ);
    proj_gemm<<<dim3(8, MKV/128), 256, PROJ_SMEM>>>(ehs, k_w, k_b, nullptr, pK);
    proj_gemm<<<dim3(8, MKV/128), 256, PROJ_SMEM>>>(ehs, v_w, v_b, nullptr, pV);

    // 2) V transpose + split
    splitT_v<<<dim3(64, Bb*NHh), 256>>>(pV, pVt);

    // 3) masked scores + softmax partials
    scores_stats<<<dim3(NTILES, LQ/128, Bb*NHh), 256, SC_SMEM>>>(pQ, pK, mask, Sout, pPmax, pPsum);

    // 4) combine partials
    stats_reduce<<<NROWS/8, 256>>>(pPmax, pPsum);

    // 5) ctx = softmax(S) @ V
    ctx_hmma<<<dim3(LQ/128, Bb*NHh), 256, CTX_SMEM>>>(Sout, pVt);

    // 6) O-projection + residual
    proj_gemm<<<dim3(8, MQ/128), 256, PROJ_SMEM>>>(pCtx, o_w, o_b, hs, pY);

    // 7) layernorm -> first output
    ln_kernel<<<MQ, 256>>>(pY, ln_w, ln_b, out);
}

// round 14
// speedup vs baseline: 1.6723x; 1.6723x over previous
#include <cuda_runtime.h>
#include <cuda_fp16.h>
#include <math.h>
#include <stdint.h>

#define Bb 2
#define LQ 1024
#define LKV 4096
#define Hh 1024
#define HD 64
#define MQ (Bb*LQ)        // 2048
#define MKV (Bb*LKV)      // 8192
#define NROWS (Bb*16*LQ)  // 32768
#define NTILES 32         // LKV/128
#define LN_EPS 1e-12f
#define NEG_INF __int_as_float(0xff800000)

// ---------------- scratch (device globals; no allocation) ----------------
__device__ float g_Q[MQ*Hh];
__device__ float g_K[MKV*Hh];
__device__ float g_V[MKV*Hh];
__device__ float g_ctx[MQ*Hh];
__device__ float g_y[MQ*Hh];
__device__ float g_rmax[NROWS];
__device__ float g_rinv[NROWS];
__device__ float g_pmax[(size_t)NROWS*NTILES];
__device__ float g_psum[(size_t)NROWS*NTILES];
// V transposed fp16 hi: [bh][d(64)][chunk(64)][kv(64)]
__device__ __half g_Vt[(size_t)Bb*16 * 64 * 64 * 64];

// ================= HMMA fp16 helper =================
__device__ __forceinline__ void mma16816h(float* d, const uint32_t* a,
                                          uint32_t b0, uint32_t b1) {
    asm volatile(
        "mma.sync.aligned.m16n8k16.row.col.f32.f16.f16.f32 "
        "{%0,%1,%2,%3}, {%4,%5,%6,%7}, {%8,%9}, {%0,%1,%2,%3};"
        : "+f"(d[0]), "+f"(d[1]), "+f"(d[2]), "+f"(d[3])
        : "r"(a[0]), "r"(a[1]), "r"(a[2]), "r"(a[3]), "r"(b0), "r"(b1));
}

#define APA 72   // A smem pitch (64 data cols [hi32|lo32] + pad)
#define APB 40   // B smem pitch (32 data cols [hi32] + pad)

// 128x32 fp32 -> [hi32|lo32] fp16 smem (A side)
__device__ __forceinline__ void stage_a32(const float* __restrict__ g, int ldg,
                                          __half* __restrict__ s, int tid)
{
#pragma unroll
    for (int i = 0; i < 4; i++) {
        int idx = tid + i * 256;
        int rr = idx >> 3, c4 = (idx & 7) * 4;
        float4 v = *(const float4*)&g[(size_t)rr * ldg + c4];
        __half h0 = __float2half(v.x), h1 = __float2half(v.y);
        __half h2 = __float2half(v.z), h3 = __float2half(v.w);
        __half l0 = __float2half(v.x - __half2float(h0));
        __half l1 = __float2half(v.y - __half2float(h1));
        __half l2 = __float2half(v.z - __half2float(h2));
        __half l3 = __float2half(v.w - __half2float(h3));
        __half2 H01; H01.x = h0; H01.y = h1;
        __half2 H23; H23.x = h2; H23.y = h3;
        __half2 L01; L01.x = l0; L01.y = l1;
        __half2 L23; L23.x = l2; L23.y = l3;
        __half* o = s + rr * APA + c4;
        *(__half2*)(o)      = H01; *(__half2*)(o + 2)      = H23;
        *(__half2*)(o + 32) = L01; *(__half2*)(o + 34) = L23;
    }
}

// 128x32 fp32 -> [hi32] fp16 smem (B side)
__device__ __forceinline__ void stage_b32(const float* __restrict__ g, int ldg,
                                          __half* __restrict__ s, int tid)
{
#pragma unroll
    for (int i = 0; i < 4; i++) {
        int idx = tid + i * 256;
        int rr = idx >> 3, c4 = (idx & 7) * 4;
        float4 v = *(const float4*)&g[(size_t)rr * ldg + c4];
        __half2 H01; H01.x = __float2half(v.x); H01.y = __float2half(v.y);
        __half2 H23; H23.x = __float2half(v.z); H23.y = __float2half(v.w);
        __half* o = s + rr * APB + c4;
        *(__half2*)(o) = H01; *(__half2*)(o + 2) = H23;
    }
}

// k-loop: 64 A-cols, B reused via kk&31. warp tile 64x32.
__device__ __forceinline__ void mma_chunk64(const __half* As, const __half* Bs,
                                            int wm, int wn, int r, int cq, float acc[4][4][4])
{
#pragma unroll
    for (int kk = 0; kk < 64; kk += 16) {
        uint32_t af[4][4];
#pragma unroll
        for (int mt = 0; mt < 4; mt++) {
            const __half* ab = &As[(wm + mt*16 + r)*APA + kk + cq*2];
            af[mt][0] = *(const uint32_t*)(ab);
            af[mt][1] = *(const uint32_t*)(ab + 8*APA);
            af[mt][2] = *(const uint32_t*)(ab + 8);
            af[mt][3] = *(const uint32_t*)(ab + 8*APA + 8);
        }
#pragma unroll
        for (int nt = 0; nt < 4; nt++) {
            const __half* bb = &Bs[(wn + nt*8 + r)*APB + (kk & 31) + cq*2];
            uint32_t b0 = *(const uint32_t*)(bb);
            uint32_t b1 = *(const uint32_t*)(bb + 8);
#pragma unroll
            for (int mt = 0; mt < 4; mt++)
                mma16816h(acc[mt][nt], af[mt], b0, b1);
        }
    }
}

// ================= projection GEMM =================
__global__ __launch_bounds__(256) void proj_gemm(
    const float* __restrict__ X, const float* __restrict__ W,
    const float* __restrict__ bias, const float* __restrict__ res,
    float* __restrict__ out)
{
    __shared__ __half As[128*APA];
    __shared__ __half Bs[128*APB];
    __shared__ float stage[128];
    const int tid = threadIdx.x, warp = tid >> 5, lane = tid & 31;
    const int m0 = blockIdx.y * 128, n0 = blockIdx.x * 128;
    const float* Ap = X + (size_t)m0 * Hh;
    const float* Bp = W + (size_t)n0 * Hh;

    if (tid < 128) stage[tid] = bias[n0 + tid];

    const int wm = (warp >> 2) * 64, wn = (warp & 3) * 32;
    const int r = lane >> 2, cq = lane & 3;

    float acc[4][4][4];
#pragma unroll
    for (int mt = 0; mt < 4; mt++)
#pragma unroll
        for (int nt = 0; nt < 4; nt++)
#pragma unroll
            for (int j = 0; j < 4; j++) acc[mt][nt][j] = 0.f;

    for (int c = 0; c < 32; c++) {
        stage_a32(Ap + c*32, Hh, As, tid);
        stage_b32(Bp + c*32, Hh, Bs, tid);
        __syncthreads();
        mma_chunk64(As, Bs, wm, wn, r, cq, acc);
        __syncthreads();
    }

#pragma unroll
    for (int mt = 0; mt < 4; mt++) {
        const int mA = m0 + wm + mt*16 + r;
#pragma unroll
        for (int nt = 0; nt < 4; nt++) {
            const int nl = wn + nt*8 + cq*2;
            const int nA = n0 + nl;
            float bx = stage[nl], by = stage[nl + 1];
            float2 v0, v1;
            v0.x = acc[mt][nt][0] + bx; v0.y = acc[mt][nt][1] + by;
            v1.x = acc[mt][nt][2] + bx; v1.y = acc[mt][nt][3] + by;
            if (res) {
                float2 r0 = *(const float2*)&res[(size_t)mA * Hh + nA];
                float2 r1 = *(const float2*)&res[(size_t)(mA+8) * Hh + nA];
                v0.x += r0.x; v0.y += r0.y; v1.x += r1.x; v1.y += r1.y;
            }
            *(float2*)&out[(size_t)mA * Hh + nA]     = v0;
            *(float2*)&out[(size_t)(mA+8) * Hh + nA] = v1;
        }
    }
}

// ================= scores + per-block softmax partials =================
__global__ __launch_bounds__(256) void scores_stats(
    const float* __restrict__ Qf, const float* __restrict__ Kf,
    const int* __restrict__ mask, float* __restrict__ S,
    float* __restrict__ pmax, float* __restrict__ psum)
{
    __shared__ __half As[128*APA];
    __shared__ __half Bs[128*APB];
    __shared__ int maskS[128];
    __shared__ float rpart[4][128];
    __shared__ float bmax[128];
    const int tid = threadIdx.x, warp = tid >> 5, lane = tid & 31;
    const int kv0 = blockIdx.x * 128, q0 = blockIdx.y * 128, bh = blockIdx.z;
    const int b = bh >> 4, h = bh & 15;

    const float* Ap = Qf + ((size_t)(b*LQ  + q0 )) * Hh + h*64;
    const float* Bp = Kf + ((size_t)(b*LKV + kv0)) * Hh + h*64;
    float* Sb = S + (size_t)bh * LQ * LKV;

    if (tid < 128) maskS[tid] = mask[b*LKV + kv0 + tid];

    const int wm = (warp >> 2) * 64, wn = (warp & 3) * 32;
    const int r = lane >> 2, cq = lane & 3;

    float acc[4][4][4];
#pragma unroll
    for (int mt = 0; mt < 4; mt++)
#pragma unroll
        for (int nt = 0; nt < 4; nt++)
#pragma unroll
            for (int j = 0; j < 4; j++) acc[mt][nt][j] = 0.f;

    for (int c = 0; c < 2; c++) {
        stage_a32(Ap + c*32, Hh, As, tid);
        stage_b32(Bp + c*32, Hh, Bs, tid);
        __syncthreads();
        mma_chunk64(As, Bs, wm, wn, r, cq, acc);
        __syncthreads();
    }

#pragma unroll
    for (int mt = 0; mt < 4; mt++) {
        const int lm = wm + mt*16 + r;
#pragma unroll
        for (int nt = 0; nt < 4; nt++) {
            const int nl = wn + nt*8 + cq*2;
            int mx = maskS[nl], my = maskS[nl + 1];
            acc[mt][nt][0] = mx ? acc[mt][nt][0] * 0.125f : NEG_INF;
            acc[mt][nt][1] = my ? acc[mt][nt][1] * 0.125f : NEG_INF;
            acc[mt][nt][2] = mx ? acc[mt][nt][2] * 0.125f : NEG_INF;
            acc[mt][nt][3] = my ? acc[mt][nt][3] * 0.125f : NEG_INF;
            float2 v0, v1;
            v0.x = acc[mt][nt][0]; v0.y = acc[mt][nt][1];
            v1.x = acc[mt][nt][2]; v1.y = acc[mt][nt][3];
            *(float2*)&Sb[(size_t)(q0 + lm)     * LKV + kv0 + nl] = v0;
            *(float2*)&Sb[(size_t)(q0 + lm + 8) * LKV + kv0 + nl] = v1;
        }
    }

#pragma unroll
    for (int mt = 0; mt < 4; mt++) {
#pragma unroll
        for (int half = 0; half < 2; half++) {
            float mrow = NEG_INF;
#pragma unroll
            for (int nt = 0; nt < 4; nt++) {
                mrow = fmaxf(mrow, acc[mt][nt][2*half + 0]);
                mrow = fmaxf(mrow, acc[mt][nt][2*half + 1]);
            }
            mrow = fmaxf(mrow, __shfl_xor_sync(0xFFFFFFFF, mrow, 1));
            mrow = fmaxf(mrow, __shfl_xor_sync(0xFFFFFFFF, mrow, 2));
            if (cq == 0) rpart[warp & 3][wm + mt*16 + r + half*8] = mrow;
        }
    }
    __syncthreads();
    if (tid < 128)
        bmax[tid] = fmaxf(fmaxf(rpart[0][tid], rpart[1][tid]),
                          fmaxf(rpart[2][tid], rpart[3][tid]));
    __syncthreads();

#pragma unroll
    for (int mt = 0; mt < 4; mt++) {
#pragma unroll
        for (int half = 0; half < 2; half++) {
            const int row = wm + mt*16 + r + half*8;
            const float bm = bmax[row];
            float srow = 0.f;
#pragma unroll
            for (int nt = 0; nt < 4; nt++) {
#pragma unroll
                for (int j = 0; j < 2; j++) {
                    float v = acc[mt][nt][2*half + j];
                    srow += (v == NEG_INF) ? 0.f : __expf(v - bm);
                }
            }
            srow += __shfl_xor_sync(0xFFFFFFFF, srow, 1);
            srow += __shfl_xor_sync(0xFFFFFFFF, srow, 2);
            if (cq == 0) rpart[warp & 3][row] = srow;
        }
    }
    __syncthreads();
    if (tid < 128) {
        float ssum = rpart[0][tid] + rpart[1][tid] + rpart[2][tid] + rpart[3][tid];
        size_t grow = (size_t)bh * LQ + q0 + tid;
        pmax[grow * NTILES + blockIdx.x] = bmax[tid];
        psum[grow * NTILES + blockIdx.x] = ssum;
    }
}

// ================= combine partial stats =================
__global__ __launch_bounds__(256) void stats_reduce(
    const float* __restrict__ pmax, const float* __restrict__ psum)
{
    const int row = blockIdx.x * 8 + (threadIdx.x >> 5);
    const int lane = threadIdx.x & 31;
    float pm = pmax[(size_t)row * NTILES + lane];
    float ps = psum[(size_t)row * NTILES + lane];
    float m = pm;
#pragma unroll
    for (int off = 16; off > 0; off >>= 1)
        m = fmaxf(m, __shfl_xor_sync(0xFFFFFFFF, m, off));
    float term = (ps > 0.f) ? ps * __expf(pm - m) : 0.f;
#pragma unroll
    for (int off = 16; off > 0; off >>= 1)
        term += __shfl_xor_sync(0xFFFFFFFF, term, off);
    if (lane == 0) { g_rmax[row] = m; g_rinv[row] = 1.0f / term; }
}

// ================= V transpose (fp16 hi only) =================
// V fp32 [b][kv][h*64+d] -> g_Vt [bh][d][chunk][kv] fp16
__global__ __launch_bounds__(256) void splitT_v(const float* __restrict__ V,
                                                __half* __restrict__ vt)
{
    __shared__ float t[64 * 65];
    const int bh = blockIdx.y, c = blockIdx.x;
    const int b = bh >> 4, h = bh & 15;
    const int tid = threadIdx.x;
    const float* src = V + ((size_t)b * LKV + c * 64) * Hh + h * 64;
#pragma unroll
    for (int i = 0; i < 16; i++) {
        int idx = tid + i * 256;
        int kv = idx >> 6, d = idx & 63;
        t[kv * 65 + d] = src[(size_t)kv * Hh + d];
    }
    __syncthreads();
#pragma unroll
    for (int i = 0; i < 2; i++) {
        int idx = tid + i * 256;      // 0..511
        int d = idx >> 3, v8 = (idx & 7) * 8;
        __half hs[8];
#pragma unroll
        for (int j = 0; j < 8; j++)
            hs[j] = __float2half(t[(v8 + j) * 65 + d]);
        *(uint4*)&vt[(((size_t)bh * 64 + d) * 64 + c) * 64 + v8] = *(uint4*)hs;
    }
}

// ---------------- ctx = softmax(S) @ V  (fp16 single-term) ----------------
#define CPA 72
__global__ __launch_bounds__(256) void ctx_hmma(const float* __restrict__ S,
                                                const __half* __restrict__ vt)
{
    __shared__ __half As[128*CPA];
    __shared__ __half Bs[64*CPA];
    __shared__ float rm[128], ri[128];

    const int tid = threadIdx.x, warp = tid >> 5, lane = tid & 31;
    const int bh = blockIdx.y, q0 = blockIdx.x * 128;
    const int b = bh >> 4, h = bh & 15;
    const int rowbase = bh * LQ + q0;

    if (tid < 128) { rm[tid] = g_rmax[rowbase + tid]; ri[tid] = g_rinv[rowbase + tid]; }
    __syncthreads();

    const float* Srow = S + (size_t)rowbase * LKV;
    const __half* vtb = vt + (size_t)bh * 64 * 64 * 64;
    const int wm = (warp >> 1) * 32, wn = (warp & 1) * 32;
    const int r = lane >> 2, cq = lane & 3;

    float acc[2][4][4];
#pragma unroll
    for (int mt = 0; mt < 2; mt++)
#pragma unroll
        for (int nt = 0; nt < 4; nt++)
#pragma unroll
            for (int j = 0; j < 4; j++) acc[mt][nt][j] = 0.f;

    for (int c = 0; c < 64; c++) {
        // P tile: exp(S-m)*inv -> fp16 -> As [128 x 64]
#pragma unroll
        for (int i = 0; i < 8; i++) {
            int idx = tid + i * 256;
            int q = idx >> 4, j = (idx & 15) * 4;
            float4 s = *(const float4*)&Srow[(size_t)q * LKV + c * 64 + j];
            float mq = rm[q], iq = ri[q];
            __half2 H01, H23;
            H01.x = __float2half(__expf(s.x - mq) * iq);
            H01.y = __float2half(__expf(s.y - mq) * iq);
            H23.x = __float2half(__expf(s.z - mq) * iq);
            H23.y = __float2half(__expf(s.w - mq) * iq);
            __half* base = &As[q * CPA + j];
            *(__half2*)(base) = H01; *(__half2*)(base + 2) = H23;
        }
        // V tile: 64 d-rows x 64 kv
#pragma unroll
        for (int i = 0; i < 2; i++) {
            int idx = tid + i * 256;
            int d = idx >> 3, v8 = (idx & 7) * 8;
            *(uint4*)&Bs[d * CPA + v8] = *(const uint4*)&vtb[((size_t)d * 64 + c) * 64 + v8];
        }
        __syncthreads();
#pragma unroll
        for (int kk = 0; kk < 64; kk += 16) {
            uint32_t af[2][4];
#pragma unroll
            for (int mt = 0; mt < 2; mt++) {
                const __half* ab = &As[(wm + mt*16 + r) * CPA + kk + cq*2];
                af[mt][0] = *(const uint32_t*)(ab);
                af[mt][1] = *(const uint32_t*)(ab + 8*CPA);
                af[mt][2] = *(const uint32_t*)(ab + 8);
                af[mt][3] = *(const uint32_t*)(ab + 8*CPA + 8);
            }
#pragma unroll
            for (int nt = 0; nt < 4; nt++) {
                const __half* bb = &Bs[(wn + nt*8 + r) * CPA + kk + cq*2];
                uint32_t b0 = *(const uint32_t*)(bb);
                uint32_t b1 = *(const uint32_t*)(bb + 8);
#pragma unroll
                for (int mt = 0; mt < 2; mt++)
                    mma16816h(acc[mt][nt], af[mt], b0, b1);
            }
        }
        __syncthreads();
    }

#pragma unroll
    for (int mt = 0; mt < 2; mt++) {
        const int q = q0 + wm + mt*16 + r;
#pragma unroll
        for (int nt = 0; nt < 4; nt++) {
            const int d = wn + nt*8 + cq*2;
            float2 v0, v1;
            v0.x = acc[mt][nt][0]; v0.y = acc[mt][nt][1];
            v1.x = acc[mt][nt][2]; v1.y = acc[mt][nt][3];
            *(float2*)&g_ctx[((size_t)(b*LQ + q))     * Hh + h*64 + d] = v0;
            *(float2*)&g_ctx[((size_t)(b*LQ + q + 8)) * Hh + h*64 + d] = v1;
        }
    }
}

// ---------------- layernorm over last dim ----------------
__global__ __launch_bounds__(256) void ln_kernel(
    const float* __restrict__ Y, const float* __restrict__ w,
    const float* __restrict__ bta, float* __restrict__ out)
{
    const int row = blockIdx.x;
    __shared__ float buf[Hh];
    __shared__ float red[256];
    const int tid = threadIdx.x;
    const float* y = Y + (size_t)row * Hh;

    float s = 0.f;
    for (int i = tid; i < Hh; i += 256) { float v = y[i]; buf[i] = v; s += v; }
    red[tid] = s; __syncthreads();
    for (int st = 128; st > 0; st >>= 1) {
        if (tid < st) red[tid] += red[tid + st];
        __syncthreads();
    }
    const float mu = red[0] * (1.0f / Hh); __syncthreads();

    float vs = 0.f;
    for (int i = tid; i < Hh; i += 256) { float dd = buf[i] - mu; vs += dd * dd; }
    red[tid] = vs; __syncthreads();
    for (int st = 128; st > 0; st >>= 1) {
        if (tid < st) red[tid] += red[tid + st];
        __syncthreads();
    }
    const float inv = rsqrtf(red[0] * (1.0f / Hh) + LN_EPS);

    for (int i = tid; i < Hh; i += 256)
        out[(size_t)row * Hh + i] = (buf[i] - mu) * inv * w[i] + bta[i];
}

// ---------------- launch ----------------
extern "C" void kernel_launch(void* const* d_in, const int* in_sizes, int n_in,
                              void* d_out, int out_size)
{
    (void)in_sizes; (void)n_in; (void)out_size;
    const float* hs   = (const float*)d_in[0];
    const float* ehs  = (const float*)d_in[1];
    const int*   mask = (const int*)  d_in[2];
    const float* q_w  = (const float*)d_in[3];
    const float* q_b  = (const float*)d_in[4];
    const float* k_w  = (const float*)d_in[5];
    const float* k_b  = (const float*)d_in[6];
    const float* v_w  = (const float*)d_in[7];
    const float* v_b  = (const float*)d_in[8];
    const float* o_w  = (const float*)d_in[9];
    const float* o_b  = (const float*)d_in[10];
    const float* ln_w = (const float*)d_in[11];
    const float* ln_b = (const float*)d_in[12];

    float* out  = (float*)d_out;
    float* Sout = out + (size_t)MQ * Hh;

    float *pQ, *pK, *pV, *pCtx, *pY, *pPmax, *pPsum;
    cudaGetSymbolAddress((void**)&pQ,    g_Q);
    cudaGetSymbolAddress((void**)&pK,    g_K);
    cudaGetSymbolAddress((void**)&pV,    g_V);
    cudaGetSymbolAddress((void**)&pCtx,  g_ctx);
    cudaGetSymbolAddress((void**)&pY,    g_y);
    cudaGetSymbolAddress((void**)&pPmax, g_pmax);
    cudaGetSymbolAddress((void**)&pPsum, g_psum);
    __half* pVt;
    cudaGetSymbolAddress((void**)&pVt, g_Vt);

    // 1) projections (fp16 2-term HMMA)
    proj_gemm<<<dim3(8, MQ/128),  256>>>(hs,  q_w, q_b, nullptr, pQ);
    proj_gemm<<<dim3(8, MKV/128), 256>>>(ehs, k_w, k_b, nullptr, pK);
    proj_gemm<<<dim3(8, MKV/128), 256>>>(ehs, v_w, v_b, nullptr, pV);

    // 2) V transpose (fp16)
    splitT_v<<<dim3(64, Bb*16), 256>>>(pV, pVt);

    // 3) masked scores + softmax partials
    scores_stats<<<dim3(NTILES, LQ/128, Bb*16), 256>>>(pQ, pK, mask, Sout, pPmax, pPsum);

    // 4) combine partials
    stats_reduce<<<NROWS/8, 256>>>(pPmax, pPsum);

    // 5) ctx = softmax(S) @ V (fp16 single-term)
    ctx_hmma<<<dim3(LQ/128, Bb*16), 256>>>(Sout, pVt);

    // 6) O-projection + residual
    proj_gemm<<<dim3(8, MQ/128), 256>>>(pCtx, o_w, o_b, hs, pY);

    // 7) layernorm -> first output
    ln_kernel<<<MQ, 256>>>(pY, ln_w, ln_b, out);
}

// round 15
// speedup vs baseline: 1.8795x; 1.1239x over previous
#include <cuda_runtime.h>
#include <cuda_fp16.h>
#include <math.h>
#include <stdint.h>

#define Bb 2
#define LQ 1024
#define LKV 4096
#define Hh 1024
#define HD 64
#define MQ (Bb*LQ)        // 2048
#define MKV (Bb*LKV)      // 8192
#define LN_EPS 1e-12f
#define NEG_INF __int_as_float(0xff800000)

// ---------------- scratch (device globals; no allocation) ----------------
__device__ float g_Q[MQ*Hh];
__device__ float g_K[MKV*Hh];
__device__ float g_V[MKV*Hh];
__device__ float g_ctx[MQ*Hh];
__device__ float g_y[MQ*Hh];
// V transposed fp16 hi: [bh][d(64)][kv(4096)]
__device__ __half g_Vt[(size_t)Bb*16 * 64 * LKV];

// ================= HMMA fp16 helper =================
__device__ __forceinline__ void mma16816h(float* d, const uint32_t* a,
                                          uint32_t b0, uint32_t b1) {
    asm volatile(
        "mma.sync.aligned.m16n8k16.row.col.f32.f16.f16.f32 "
        "{%0,%1,%2,%3}, {%4,%5,%6,%7}, {%8,%9}, {%0,%1,%2,%3};"
        : "+f"(d[0]), "+f"(d[1]), "+f"(d[2]), "+f"(d[3])
        : "r"(a[0]), "r"(a[1]), "r"(a[2]), "r"(a[3]), "r"(b0), "r"(b1));
}

__device__ __forceinline__ uint32_t pack_h2(float a, float b) {
    __half2 h = __floats2half2_rn(a, b);
    return *(uint32_t*)&h;
}

#define APA 72   // A smem pitch (64 data cols [hi32|lo32] + pad)
#define APB 40   // B smem pitch (32 data cols [hi32] + pad)

// 128x32 fp32 -> [hi32|lo32] fp16 smem (A side)
__device__ __forceinline__ void stage_a32(const float* __restrict__ g, int ldg,
                                          __half* __restrict__ s, int tid)
{
#pragma unroll
    for (int i = 0; i < 4; i++) {
        int idx = tid + i * 256;
        int rr = idx >> 3, c4 = (idx & 7) * 4;
        float4 v = *(const float4*)&g[(size_t)rr * ldg + c4];
        __half h0 = __float2half(v.x), h1 = __float2half(v.y);
        __half h2 = __float2half(v.z), h3 = __float2half(v.w);
        __half l0 = __float2half(v.x - __half2float(h0));
        __half l1 = __float2half(v.y - __half2float(h1));
        __half l2 = __float2half(v.z - __half2float(h2));
        __half l3 = __float2half(v.w - __half2float(h3));
        __half2 H01; H01.x = h0; H01.y = h1;
        __half2 H23; H23.x = h2; H23.y = h3;
        __half2 L01; L01.x = l0; L01.y = l1;
        __half2 L23; L23.x = l2; L23.y = l3;
        __half* o = s + rr * APA + c4;
        *(__half2*)(o)      = H01; *(__half2*)(o + 2)      = H23;
        *(__half2*)(o + 32) = L01; *(__half2*)(o + 34) = L23;
    }
}

// 128x32 fp32 -> [hi32] fp16 smem (B side)
__device__ __forceinline__ void stage_b32(const float* __restrict__ g, int ldg,
                                          __half* __restrict__ s, int tid)
{
#pragma unroll
    for (int i = 0; i < 4; i++) {
        int idx = tid + i * 256;
        int rr = idx >> 3, c4 = (idx & 7) * 4;
        float4 v = *(const float4*)&g[(size_t)rr * ldg + c4];
        __half2 H01; H01.x = __float2half(v.x); H01.y = __float2half(v.y);
        __half2 H23; H23.x = __float2half(v.z); H23.y = __float2half(v.w);
        __half* o = s + rr * APB + c4;
        *(__half2*)(o) = H01; *(__half2*)(o + 2) = H23;
    }
}

// k-loop: 64 A-cols, B reused via kk&31. warp tile 64x32.
__device__ __forceinline__ void mma_chunk64(const __half* As, const __half* Bs,
                                            int wm, int wn, int r, int cq, float acc[4][4][4])
{
#pragma unroll
    for (int kk = 0; kk < 64; kk += 16) {
        uint32_t af[4][4];
#pragma unroll
        for (int mt = 0; mt < 4; mt++) {
            const __half* ab = &As[(wm + mt*16 + r)*APA + kk + cq*2];
            af[mt][0] = *(const uint32_t*)(ab);
            af[mt][1] = *(const uint32_t*)(ab + 8*APA);
            af[mt][2] = *(const uint32_t*)(ab + 8);
            af[mt][3] = *(const uint32_t*)(ab + 8*APA + 8);
        }
#pragma unroll
        for (int nt = 0; nt < 4; nt++) {
            const __half* bb = &Bs[(wn + nt*8 + r)*APB + (kk & 31) + cq*2];
            uint32_t b0 = *(const uint32_t*)(bb);
            uint32_t b1 = *(const uint32_t*)(bb + 8);
#pragma unroll
            for (int mt = 0; mt < 4; mt++)
                mma16816h(acc[mt][nt], af[mt], b0, b1);
        }
    }
}

// ================= projection GEMM (unchanged from R14) =================
__global__ __launch_bounds__(256) void proj_gemm(
    const float* __restrict__ X, const float* __restrict__ W,
    const float* __restrict__ bias, const float* __restrict__ res,
    float* __restrict__ out)
{
    __shared__ __half As[128*APA];
    __shared__ __half Bs[128*APB];
    __shared__ float stage[128];
    const int tid = threadIdx.x, warp = tid >> 5, lane = tid & 31;
    const int m0 = blockIdx.y * 128, n0 = blockIdx.x * 128;
    const float* Ap = X + (size_t)m0 * Hh;
    const float* Bp = W + (size_t)n0 * Hh;

    if (tid < 128) stage[tid] = bias[n0 + tid];

    const int wm = (warp >> 2) * 64, wn = (warp & 3) * 32;
    const int r = lane >> 2, cq = lane & 3;

    float acc[4][4][4];
#pragma unroll
    for (int mt = 0; mt < 4; mt++)
#pragma unroll
        for (int nt = 0; nt < 4; nt++)
#pragma unroll
            for (int j = 0; j < 4; j++) acc[mt][nt][j] = 0.f;

    for (int c = 0; c < 32; c++) {
        stage_a32(Ap + c*32, Hh, As, tid);
        stage_b32(Bp + c*32, Hh, Bs, tid);
        __syncthreads();
        mma_chunk64(As, Bs, wm, wn, r, cq, acc);
        __syncthreads();
    }

#pragma unroll
    for (int mt = 0; mt < 4; mt++) {
        const int mA = m0 + wm + mt*16 + r;
#pragma unroll
        for (int nt = 0; nt < 4; nt++) {
            const int nl = wn + nt*8 + cq*2;
            const int nA = n0 + nl;
            float bx = stage[nl], by = stage[nl + 1];
            float2 v0, v1;
            v0.x = acc[mt][nt][0] + bx; v0.y = acc[mt][nt][1] + by;
            v1.x = acc[mt][nt][2] + bx; v1.y = acc[mt][nt][3] + by;
            if (res) {
                float2 r0 = *(const float2*)&res[(size_t)mA * Hh + nA];
                float2 r1 = *(const float2*)&res[(size_t)(mA+8) * Hh + nA];
                v0.x += r0.x; v0.y += r0.y; v1.x += r1.x; v1.y += r1.y;
            }
            *(float2*)&out[(size_t)mA * Hh + nA]     = v0;
            *(float2*)&out[(size_t)(mA+8) * Hh + nA] = v1;
        }
    }
}

// ================= V transpose (fp16 hi) -> [bh][d][kv] =================
__global__ __launch_bounds__(256) void splitT_v(const float* __restrict__ V,
                                                __half* __restrict__ vt)
{
    __shared__ float t[64 * 65];
    const int bh = blockIdx.y, c = blockIdx.x;
    const int b = bh >> 4, h = bh & 15;
    const int tid = threadIdx.x;
    const float* src = V + ((size_t)b * LKV + c * 64) * Hh + h * 64;
#pragma unroll
    for (int i = 0; i < 16; i++) {
        int idx = tid + i * 256;
        int kv = idx >> 6, d = idx & 63;
        t[kv * 65 + d] = src[(size_t)kv * Hh + d];
    }
    __syncthreads();
#pragma unroll
    for (int i = 0; i < 2; i++) {
        int idx = tid + i * 256;      // 0..511
        int d = idx >> 3, v8 = (idx & 7) * 8;
        __half hs[8];
#pragma unroll
        for (int j = 0; j < 8; j++)
            hs[j] = __float2half(t[(v8 + j) * 65 + d]);
        *(uint4*)&vt[((size_t)bh * 64 + d) * LKV + c * 64 + v8] = *(uint4*)hs;
    }
}

// ================= fused flash attention =================
// grid (LQ/64, 32), block 128 (4 warps; each warp: 16 q rows x full kv tile)
#define QP 136
#define KP 72
#define VP 136
#define FA_SMEM (64*QP*2 + 128*KP*2 + 64*VP*2 + 512)
__global__ __launch_bounds__(128) void flash_attn(
    const float* __restrict__ Qf, const float* __restrict__ Kf,
    const __half* __restrict__ vt, const int* __restrict__ mask,
    float* __restrict__ S)
{
    extern __shared__ char sm8[];
    __half* Qs = (__half*)sm8;
    __half* Ks = Qs + 64*QP;
    __half* Vs = Ks + 128*KP;
    int* maskS = (int*)(Vs + 64*VP);

    const int tid = threadIdx.x, warp = tid >> 5, lane = tid & 31;
    const int q0 = blockIdx.x * 64, bh = blockIdx.y;
    const int b = bh >> 4, h = bh & 15;
    const int r = lane >> 2, cq = lane & 3;
    const int wq = warp * 16;

    // stage Q tile once: 64 rows x 64 fp32 -> [hi64|lo64] fp16
    {
        const float* Ap = Qf + ((size_t)(b*LQ + q0)) * Hh + h*64;
#pragma unroll
        for (int i = 0; i < 8; i++) {
            int idx = tid + i * 128;      // 0..1023
            int rr = idx >> 4, c4 = (idx & 15) * 4;
            float4 v = *(const float4*)&Ap[(size_t)rr * Hh + c4];
            __half h0=__float2half(v.x), h1=__float2half(v.y);
            __half h2=__float2half(v.z), h3=__float2half(v.w);
            __half2 H01; H01.x=h0; H01.y=h1;
            __half2 H23; H23.x=h2; H23.y=h3;
            __half2 L01; L01.x=__float2half(v.x-__half2float(h0)); L01.y=__float2half(v.y-__half2float(h1));
            __half2 L23; L23.x=__float2half(v.z-__half2float(h2)); L23.y=__float2half(v.w-__half2float(h3));
            __half* o = Qs + rr*QP + c4;
            *(__half2*)o      = H01; *(__half2*)(o+2)  = H23;
            *(__half2*)(o+64) = L01; *(__half2*)(o+66) = L23;
        }
    }

    float cacc[8][4];
#pragma unroll
    for (int nt = 0; nt < 8; nt++)
#pragma unroll
        for (int j = 0; j < 4; j++) cacc[nt][j] = 0.f;
    float mrun0 = NEG_INF, mrun1 = NEG_INF, srun0 = 0.f, srun1 = 0.f;

    const float* Kbase = Kf + (size_t)(b*LKV) * Hh + h*64;
    const __half* Vbase = vt + (size_t)bh * 64 * LKV;
    float* Sb = S + ((size_t)bh * LQ + q0) * LKV;

    for (int t = 0; t < 32; t++) {
        const int kv0 = t * 128;
        __syncthreads();   // previous tile's smem reads complete
        // K tile: 128 kv rows x 64 hd -> fp16 hi
#pragma unroll
        for (int i = 0; i < 16; i++) {
            int idx = tid + i * 128;     // 0..2047
            int rr = idx >> 4, c4 = (idx & 15) * 4;
            float4 v = *(const float4*)&Kbase[(size_t)(kv0+rr) * Hh + c4];
            __half2 H01; H01.x=__float2half(v.x); H01.y=__float2half(v.y);
            __half2 H23; H23.x=__float2half(v.z); H23.y=__float2half(v.w);
            __half* o = Ks + rr*KP + c4;
            *(__half2*)o = H01; *(__half2*)(o+2) = H23;
        }
        // V tile: 64 d rows x 128 kv fp16
#pragma unroll
        for (int i = 0; i < 8; i++) {
            int idx = tid + i * 128;     // 0..1023
            int d = idx >> 4, v8 = (idx & 15) * 8;
            *(uint4*)&Vs[d*VP + v8] = *(const uint4*)&Vbase[(size_t)d * LKV + kv0 + v8];
        }
        maskS[tid] = mask[b*LKV + kv0 + tid];
        __syncthreads();

        // ---- scores: S tile fragments, k' = 128 = [Qhi|Qlo] ----
        float sacc[16][4];
#pragma unroll
        for (int j = 0; j < 16; j++)
#pragma unroll
            for (int k = 0; k < 4; k++) sacc[j][k] = 0.f;
#pragma unroll
        for (int kk = 0; kk < 128; kk += 16) {
            const __half* ab = &Qs[(wq + r)*QP + kk + cq*2];
            uint32_t a[4];
            a[0] = *(const uint32_t*)(ab);
            a[1] = *(const uint32_t*)(ab + 8*QP);
            a[2] = *(const uint32_t*)(ab + 8);
            a[3] = *(const uint32_t*)(ab + 8*QP + 8);
#pragma unroll
            for (int j = 0; j < 16; j++) {
                const __half* bb = &Ks[(j*8 + r)*KP + (kk & 63) + cq*2];
                uint32_t b0 = *(const uint32_t*)(bb);
                uint32_t b1 = *(const uint32_t*)(bb + 8);
                mma16816h(sacc[j], a, b0, b1);
            }
        }

        // ---- mask + scale, write S ----
#pragma unroll
        for (int j = 0; j < 16; j++) {
            int c0i = j*8 + cq*2;
            int mx = maskS[c0i], my = maskS[c0i + 1];
            sacc[j][0] = mx ? sacc[j][0]*0.125f : NEG_INF;
            sacc[j][1] = my ? sacc[j][1]*0.125f : NEG_INF;
            sacc[j][2] = mx ? sacc[j][2]*0.125f : NEG_INF;
            sacc[j][3] = my ? sacc[j][3]*0.125f : NEG_INF;
            int cc = kv0 + c0i;
            *(float2*)&Sb[(size_t)(wq + r)     * LKV + cc] = make_float2(sacc[j][0], sacc[j][1]);
            *(float2*)&Sb[(size_t)(wq + r + 8) * LKV + cc] = make_float2(sacc[j][2], sacc[j][3]);
        }

        // ---- online softmax ----
        float mt0 = NEG_INF, mt1 = NEG_INF;
#pragma unroll
        for (int j = 0; j < 16; j++) {
            mt0 = fmaxf(mt0, fmaxf(sacc[j][0], sacc[j][1]));
            mt1 = fmaxf(mt1, fmaxf(sacc[j][2], sacc[j][3]));
        }
        mt0 = fmaxf(mt0, __shfl_xor_sync(0xFFFFFFFF, mt0, 1));
        mt0 = fmaxf(mt0, __shfl_xor_sync(0xFFFFFFFF, mt0, 2));
        mt1 = fmaxf(mt1, __shfl_xor_sync(0xFFFFFFFF, mt1, 1));
        mt1 = fmaxf(mt1, __shfl_xor_sync(0xFFFFFFFF, mt1, 2));
        float mn0 = fmaxf(mrun0, mt0), mn1 = fmaxf(mrun1, mt1);
        float al0 = (mrun0 == NEG_INF) ? 0.f : __expf(mrun0 - mn0);
        float al1 = (mrun1 == NEG_INF) ? 0.f : __expf(mrun1 - mn1);
#pragma unroll
        for (int nt = 0; nt < 8; nt++) {
            cacc[nt][0] *= al0; cacc[nt][1] *= al0;
            cacc[nt][2] *= al1; cacc[nt][3] *= al1;
        }
        float rs0 = 0.f, rs1 = 0.f;
#pragma unroll
        for (int j = 0; j < 16; j++) {
            float p0 = (sacc[j][0] == NEG_INF) ? 0.f : __expf(sacc[j][0] - mn0);
            float p1 = (sacc[j][1] == NEG_INF) ? 0.f : __expf(sacc[j][1] - mn0);
            float p2 = (sacc[j][2] == NEG_INF) ? 0.f : __expf(sacc[j][2] - mn1);
            float p3 = (sacc[j][3] == NEG_INF) ? 0.f : __expf(sacc[j][3] - mn1);
            sacc[j][0] = p0; sacc[j][1] = p1; sacc[j][2] = p2; sacc[j][3] = p3;
            rs0 += p0 + p1; rs1 += p2 + p3;
        }
        rs0 += __shfl_xor_sync(0xFFFFFFFF, rs0, 1);
        rs0 += __shfl_xor_sync(0xFFFFFFFF, rs0, 2);
        rs1 += __shfl_xor_sync(0xFFFFFFFF, rs1, 1);
        rs1 += __shfl_xor_sync(0xFFFFFFFF, rs1, 2);
        srun0 = srun0 * al0 + rs0;
        srun1 = srun1 * al1 + rs1;
        mrun0 = mn0; mrun1 = mn1;

        // ---- P @ V: P fragments from sacc (C->A register pairing) ----
#pragma unroll
        for (int tt = 0; tt < 8; tt++) {
            uint32_t a[4];
            a[0] = pack_h2(sacc[2*tt][0],   sacc[2*tt][1]);
            a[1] = pack_h2(sacc[2*tt][2],   sacc[2*tt][3]);
            a[2] = pack_h2(sacc[2*tt+1][0], sacc[2*tt+1][1]);
            a[3] = pack_h2(sacc[2*tt+1][2], sacc[2*tt+1][3]);
#pragma unroll
            for (int nt = 0; nt < 8; nt++) {
                const __half* bb = &Vs[(nt*8 + r)*VP + tt*16 + cq*2];
                uint32_t b0 = *(const uint32_t*)(bb);
                uint32_t b1 = *(const uint32_t*)(bb + 8);
                mma16816h(cacc[nt], a, b0, b1);
            }
        }
    }

    // ---- epilogue: ctx = cacc / sum ----
    float inv0 = 1.f / srun0, inv1 = 1.f / srun1;
    const int q = q0 + wq + r;
#pragma unroll
    for (int nt = 0; nt < 8; nt++) {
        int d = nt*8 + cq*2;
        *(float2*)&g_ctx[((size_t)(b*LQ + q))     * Hh + h*64 + d] =
            make_float2(cacc[nt][0]*inv0, cacc[nt][1]*inv0);
        *(float2*)&g_ctx[((size_t)(b*LQ + q + 8)) * Hh + h*64 + d] =
            make_float2(cacc[nt][2]*inv1, cacc[nt][3]*inv1);
    }
}

// ---------------- layernorm over last dim ----------------
__global__ __launch_bounds__(256) void ln_kernel(
    const float* __restrict__ Y, const float* __restrict__ w,
    const float* __restrict__ bta, float* __restrict__ out)
{
    const int row = blockIdx.x;
    __shared__ float buf[Hh];
    __shared__ float red[256];
    const int tid = threadIdx.x;
    const float* y = Y + (size_t)row * Hh;

    float s = 0.f;
    for (int i = tid; i < Hh; i += 256) { float v = y[i]; buf[i] = v; s += v; }
    red[tid] = s; __syncthreads();
    for (int st = 128; st > 0; st >>= 1) {
        if (tid < st) red[tid] += red[tid + st];
        __syncthreads();
    }
    const float mu = red[0] * (1.0f / Hh); __syncthreads();

    float vs = 0.f;
    for (int i = tid; i < Hh; i += 256) { float dd = buf[i] - mu; vs += dd * dd; }
    red[tid] = vs; __syncthreads();
    for (int st = 128; st > 0; st >>= 1) {
        if (tid < st) red[tid] += red[tid + st];
        __syncthreads();
    }
    const float inv = rsqrtf(red[0] * (1.0f / Hh) + LN_EPS);

    for (int i = tid; i < Hh; i += 256)
        out[(size_t)row * Hh + i] = (buf[i] - mu) * inv * w[i] + bta[i];
}

// ---------------- launch ----------------
extern "C" void kernel_launch(void* const* d_in, const int* in_sizes, int n_in,
                              void* d_out, int out_size)
{
    (void)in_sizes; (void)n_in; (void)out_size;
    const float* hs   = (const float*)d_in[0];
    const float* ehs  = (const float*)d_in[1];
    const int*   mask = (const int*)  d_in[2];
    const float* q_w  = (const float*)d_in[3];
    const float* q_b  = (const float*)d_in[4];
    const float* k_w  = (const float*)d_in[5];
    const float* k_b  = (const float*)d_in[6];
    const float* v_w  = (const float*)d_in[7];
    const float* v_b  = (const float*)d_in[8];
    const float* o_w  = (const float*)d_in[9];
    const float* o_b  = (const float*)d_in[10];
    const float* ln_w = (const float*)d_in[11];
    const float* ln_b = (const float*)d_in[12];

    float* out  = (float*)d_out;
    float* Sout = out + (size_t)MQ * Hh;

    float *pQ, *pK, *pV, *pCtx, *pY;
    cudaGetSymbolAddress((void**)&pQ,   g_Q);
    cudaGetSymbolAddress((void**)&pK,   g_K);
    cudaGetSymbolAddress((void**)&pV,   g_V);
    cudaGetSymbolAddress((void**)&pCtx, g_ctx);
    cudaGetSymbolAddress((void**)&pY,   g_y);
    __half* pVt;
    cudaGetSymbolAddress((void**)&pVt, g_Vt);

    cudaFuncSetAttribute(flash_attn, cudaFuncAttributeMaxDynamicSharedMemorySize, FA_SMEM);

    // 1) projections (fp16 2-term HMMA)
    proj_gemm<<<dim3(8, MQ/128),  256>>>(hs,  q_w, q_b, nullptr, pQ);
    proj_gemm<<<dim3(8, MKV/128), 256>>>(ehs, k_w, k_b, nullptr, pK);
    proj_gemm<<<dim3(8, MKV/128), 256>>>(ehs, v_w, v_b, nullptr, pV);

    // 2) V transpose (fp16, [bh][d][kv])
    splitT_v<<<dim3(64, Bb*16), 256>>>(pV, pVt);

    // 3) fused: masked scores -> S output + online softmax + P@V -> ctx
    flash_attn<<<dim3(LQ/64, Bb*16), 128, FA_SMEM>>>(pQ, pK, pVt, mask, Sout);

    // 4) O-projection + residual
    proj_gemm<<<dim3(8, MQ/128), 256>>>(pCtx, o_w, o_b, hs, pY);

    // 5) layernorm -> first output
    ln_kernel<<<MQ, 256>>>(pY, ln_w, ln_b, out);
}